// round 6
// baseline (speedup 1.0000x reference)
#include <cuda_runtime.h>
#include <cuda_bf16.h>

// ---------------------------------------------------------------------------
// ParamMakeFeature: fold rotation into MLP weights, then run a packed-f32x2
// 3->15->15->15 MLP, 4 points per thread (2 f32x2 lanes sharing weight loads).
//
// KEY STRUCTURE (R6): weights stored TRANSPOSED; reductions run k-outer with
// 30 resident accumulators (15 outputs x 2 lanes) instead of serial 15-deep
// dot-product chains. This removes the FFMA2 dep-chain + LDS-on-critical-path
// stalls that capped per-warp issue at ~40%.
//
// All MLP loops FULLY unrolled: h/acc arrays must be compile-time indexed or
// ptxas demotes them to local memory (R4 regression).
// ---------------------------------------------------------------------------

typedef unsigned long long u64;

#define FEAT 15
#define MAXB 32

// per-batch packed params (u64 = duplicated f32x2 pair), 16 u64 per row:
//  [0,64):     stage1T, 4 rows x 16:  row k(0..2): W1R[f][k] at col f; row 3: b1
//  [64,320):   stage2T, 16 rows x 16: row f(0..14): W2[g][f] at col g; row 15: b2
//  [320,576):  stage3T, 16 rows x 16: row f(0..14): M3[p][f] at col p; row 15: c3
#define S1_OFF 0
#define S2_OFF 64
#define S3_OFF 320
#define PAR_STRIDE 576

__device__ u64 g_params[MAXB * PAR_STRIDE];

__device__ __forceinline__ u64 pk2(float lo, float hi) {
    u64 r; asm("mov.b64 %0, {%1,%2};" : "=l"(r) : "f"(lo), "f"(hi)); return r;
}
__device__ __forceinline__ void upk2(u64 v, float& lo, float& hi) {
    asm("mov.b64 {%0,%1}, %2;" : "=f"(lo), "=f"(hi) : "l"(v));
}
__device__ __forceinline__ u64 ffma2(u64 a, u64 b, u64 c) {
    u64 d; asm("fma.rn.f32x2 %0, %1, %2, %3;" : "=l"(d) : "l"(a), "l"(b), "l"(c));
    return d;
}
__device__ __forceinline__ u64 relu2(u64 v) {
    float lo, hi; upk2(v, lo, hi);
    lo = fmaxf(lo, 0.f); hi = fmaxf(hi, 0.f);
    return pk2(lo, hi);
}

// ---------------------------------------------------------------------------
// Precompute kernel: one block per batch. Builds W1R = W1*R^T, D-blocks,
// M3 = Dblk*W3, c3 = Dblk*b3; writes duplicated f32x2 pairs, TRANSPOSED rows.
// ---------------------------------------------------------------------------
__global__ void precompute_kernel(
    const float* __restrict__ R_all,
    const float* __restrict__ W1, const float* __restrict__ b1,
    const float* __restrict__ W2, const float* __restrict__ b2,
    const float* __restrict__ W3, const float* __restrict__ b3,
    const float* __restrict__ Q1, const float* __restrict__ Q2,
    const float* __restrict__ Q3)
{
    const int b = blockIdx.x;
    const int tid = threadIdx.x;

    __shared__ float R[9];
    __shared__ float K2[81];
    __shared__ float K3[729];
    __shared__ float E2[9][5];
    __shared__ float E3[27][7];
    __shared__ float D1[3][3], D2[5][5], D3[7][7];
    __shared__ float M3[15][15], c3[15], W1Rs[15][3];

    if (tid < 9) R[tid] = R_all[b * 9 + tid];
    __syncthreads();

    if (tid < 81) {
        int row = tid / 9, col = tid % 9;
        int i = row / 3, k = row % 3, j = col / 3, l = col % 3;
        K2[tid] = R[i * 3 + j] * R[k * 3 + l];
    } else if (tid >= 96 && tid < 105) {
        int t = tid - 96, p = t / 3, q = t % 3;
        float s = 0.f;
        for (int i = 0; i < 3; i++)
            for (int j = 0; j < 3; j++)
                s += Q1[p * 3 + i] * R[i * 3 + j] * Q1[q * 3 + j];
        D1[p][q] = s;
    } else if (tid >= 112 && tid < 157) {
        int t = tid - 112, f = t / 3, j = t % 3;
        float s = 0.f;
        for (int i = 0; i < 3; i++) s += W1[f * 3 + i] * R[j * 3 + i];
        W1Rs[f][j] = s;
    }
    __syncthreads();

    if (tid < 45) {
        int i = tid / 5, q = tid % 5;
        float s = 0.f;
        for (int j = 0; j < 9; j++) s += K2[i * 9 + j] * Q2[q * 9 + j];
        E2[i][q] = s;
    }
    for (int idx = tid; idx < 729; idx += blockDim.x) {
        int row = idx / 27, col = idx % 27;
        int a = row / 3, m = row % 3, bb = col / 3, nn = col % 3;
        K3[idx] = K2[a * 9 + bb] * R[m * 3 + nn];
    }
    __syncthreads();

    if (tid < 25) {
        int p = tid / 5, q = tid % 5;
        float s = 0.f;
        for (int i = 0; i < 9; i++) s += Q2[p * 9 + i] * E2[i][q];
        D2[p][q] = s;
    } else if (tid >= 32 && tid < 32 + 189) {
        int t = tid - 32, u = t / 7, q = t % 7;
        float s = 0.f;
        for (int v = 0; v < 27; v++) s += K3[u * 27 + v] * Q3[q * 27 + v];
        E3[u][q] = s;
    }
    __syncthreads();

    if (tid < 49) {
        int p = tid / 7, q = tid % 7;
        float s = 0.f;
        for (int u = 0; u < 27; u++) s += Q3[p * 27 + u] * E3[u][q];
        D3[p][q] = s;
    }
    __syncthreads();

    if (tid < 225) {
        int p = tid / 15, f = tid % 15;
        float s = 0.f;
        if (p < 3)       { for (int q = 0; q < 3; q++) s += D1[p][q]     * W3[q * 15 + f]; }
        else if (p < 8)  { for (int q = 0; q < 5; q++) s += D2[p - 3][q] * W3[(3 + q) * 15 + f]; }
        else             { for (int q = 0; q < 7; q++) s += D3[p - 8][q] * W3[(8 + q) * 15 + f]; }
        M3[p][f] = s;
    } else if (tid < 240) {
        int p = tid - 225;
        float s = 0.f;
        if (p < 3)       { for (int q = 0; q < 3; q++) s += D1[p][q]     * b3[q]; }
        else if (p < 8)  { for (int q = 0; q < 5; q++) s += D2[p - 3][q] * b3[3 + q]; }
        else             { for (int q = 0; q < 7; q++) s += D3[p - 8][q] * b3[8 + q]; }
        c3[p] = s;
    }
    __syncthreads();

    // write duplicated-pair params, TRANSPOSED padded layout
    u64* dst = g_params + (size_t)b * PAR_STRIDE;
    for (int idx = tid; idx < PAR_STRIDE; idx += blockDim.x) {
        float v = 0.f;
        if (idx < S2_OFF) {
            int k = idx >> 4, f = idx & 15;          // stage1T row k, col f
            if (f < 15) v = (k < 3) ? W1Rs[f][k] : b1[f];
        } else if (idx < S3_OFF) {
            int r = idx - S2_OFF, f = r >> 4, g = r & 15;  // stage2T row f, col g
            if (g < 15) v = (f < 15) ? W2[g * 15 + f] : b2[g];
        } else {
            int r = idx - S3_OFF, f = r >> 4, p = r & 15;  // stage3T row f, col p
            if (p < 15) v = (f < 15) ? M3[p][f] : c3[p];
        }
        dst[idx] = pk2(v, v);
    }
}

// ---------------------------------------------------------------------------
// Main kernel: each thread processes 4 adjacent points as 2 f32x2 lanes.
// k-outer accumulator-resident reductions; weights via broadcast LDS.128.
// ---------------------------------------------------------------------------
#define THREADS 128

// init 15 dup-pair accumulators (both lanes) from a 16-u64 bias row
#define INIT_ACCS(accA, accB, rowptr) do {                                   \
    const ulonglong2* _r = (const ulonglong2*)(rowptr);                      \
    _Pragma("unroll")                                                        \
    for (int _j = 0; _j < 7; _j++) {                                         \
        ulonglong2 _w = _r[_j];                                              \
        accA[2*_j] = _w.x;   accB[2*_j] = _w.x;                              \
        accA[2*_j+1] = _w.y; accB[2*_j+1] = _w.y;                            \
    }                                                                        \
    u64 _w14 = ((const u64*)(rowptr))[14];                                   \
    accA[14] = _w14; accB[14] = _w14;                                        \
} while (0)

// rank-1 update: acc[g] += h * wrow[g] for g=0..14, both lanes
#define RANK1(accA, accB, hA, hB, rowptr) do {                               \
    const ulonglong2* _r = (const ulonglong2*)(rowptr);                      \
    u64 _hA = (hA), _hB = (hB);                                              \
    _Pragma("unroll")                                                        \
    for (int _j = 0; _j < 7; _j++) {                                         \
        ulonglong2 _w = _r[_j];                                              \
        accA[2*_j]   = ffma2(_hA, _w.x, accA[2*_j]);                         \
        accB[2*_j]   = ffma2(_hB, _w.x, accB[2*_j]);                         \
        accA[2*_j+1] = ffma2(_hA, _w.y, accA[2*_j+1]);                       \
        accB[2*_j+1] = ffma2(_hB, _w.y, accB[2*_j+1]);                       \
    }                                                                        \
    u64 _w14 = ((const u64*)(rowptr))[14];                                   \
    accA[14] = ffma2(_hA, _w14, accA[14]);                                   \
    accB[14] = ffma2(_hB, _w14, accB[14]);                                   \
} while (0)

__global__ __launch_bounds__(THREADS, 3)
void mf_main_kernel(const float* __restrict__ x, float* __restrict__ out, int N)
{
    const int b = blockIdx.y;
    __shared__ __align__(16) u64 sw[PAR_STRIDE];
    {
        const u64* src = g_params + (size_t)b * PAR_STRIDE;
        for (int i = threadIdx.x; i < PAR_STRIDE; i += THREADS) sw[i] = src[i];
    }
    __syncthreads();

    const int t = blockIdx.x * THREADS + threadIdx.x;
    const int quads = N >> 2;

    const float* xb = x + (size_t)b * 3 * N;
    float* __restrict__ ob = out + (size_t)b * FEAT * N;

    if (t < quads) {
        float4 a0 = __ldcs((const float4*)(xb                 ) + t);
        float4 a1 = __ldcs((const float4*)(xb + N             ) + t);
        float4 a2 = __ldcs((const float4*)(xb + 2 * (size_t)N ) + t);
        u64 x0A = pk2(a0.x, a0.y), x0B = pk2(a0.z, a0.w);
        u64 x1A = pk2(a1.x, a1.y), x1B = pk2(a1.z, a1.w);
        u64 x2A = pk2(a2.x, a2.y), x2B = pk2(a2.z, a2.w);

        // ---- stage 1: h1 = relu(W1R*x + b1), k-outer over the 3 inputs ----
        u64 h1A[FEAT], h1B[FEAT];
        INIT_ACCS(h1A, h1B, sw + S1_OFF + 3 * 16);       // bias row
        RANK1(h1A, h1B, x0A, x0B, sw + S1_OFF + 0 * 16);
        RANK1(h1A, h1B, x1A, x1B, sw + S1_OFF + 1 * 16);
        RANK1(h1A, h1B, x2A, x2B, sw + S1_OFF + 2 * 16);
#pragma unroll
        for (int f = 0; f < FEAT; f++) { h1A[f] = relu2(h1A[f]); h1B[f] = relu2(h1B[f]); }

        // ---- stage 2: h2 = relu(W2*h1 + b2), k-outer over h1 ----
        u64 h2A[FEAT], h2B[FEAT];
        INIT_ACCS(h2A, h2B, sw + S2_OFF + 15 * 16);      // bias row
#pragma unroll
        for (int f = 0; f < FEAT; f++)
            RANK1(h2A, h2B, h1A[f], h1B[f], sw + S2_OFF + f * 16);
#pragma unroll
        for (int g = 0; g < FEAT; g++) { h2A[g] = relu2(h2A[g]); h2B[g] = relu2(h2B[g]); }

        // ---- stage 3: y = M3*h2 + c3, k-outer over h2 ----
        u64 oA[FEAT], oB[FEAT];
        INIT_ACCS(oA, oB, sw + S3_OFF + 15 * 16);        // bias row
#pragma unroll
        for (int f = 0; f < FEAT; f++)
            RANK1(oA, oB, h2A[f], h2B[f], sw + S3_OFF + f * 16);

#pragma unroll
        for (int pp = 0; pp < FEAT; pp++) {
            float4 st;
            upk2(oA[pp], st.x, st.y);
            upk2(oB[pp], st.z, st.w);
            __stcs((float4*)(ob + (size_t)pp * N) + t, st);
        }
    } else {
        // scalar tail for N % 4 leftover points (lo half of duplicated pairs)
        const int rem = N & 3;
        const int tp = t - quads;
        if (tp < rem) {
            const int p = (quads << 2) + tp;
            const float* swf = (const float*)sw;
            float xv[3] = { xb[p], xb[N + p], xb[2 * (size_t)N + p] };
            float h1[FEAT], h2[FEAT], o[FEAT];
            for (int f = 0; f < FEAT; f++) h1[f] = swf[(S1_OFF + 3 * 16 + f) * 2];
            for (int k = 0; k < 3; k++)
                for (int f = 0; f < FEAT; f++)
                    h1[f] += xv[k] * swf[(S1_OFF + k * 16 + f) * 2];
            for (int f = 0; f < FEAT; f++) h1[f] = fmaxf(h1[f], 0.f);

            for (int g = 0; g < FEAT; g++) h2[g] = swf[(S2_OFF + 15 * 16 + g) * 2];
            for (int f = 0; f < FEAT; f++)
                for (int g = 0; g < FEAT; g++)
                    h2[g] += h1[f] * swf[(S2_OFF + f * 16 + g) * 2];
            for (int g = 0; g < FEAT; g++) h2[g] = fmaxf(h2[g], 0.f);

            for (int pp = 0; pp < FEAT; pp++) o[pp] = swf[(S3_OFF + 15 * 16 + pp) * 2];
            for (int f = 0; f < FEAT; f++)
                for (int pp = 0; pp < FEAT; pp++)
                    o[pp] += h2[f] * swf[(S3_OFF + f * 16 + pp) * 2];
            for (int pp = 0; pp < FEAT; pp++)
                ob[(size_t)pp * N + p] = o[pp];
        }
    }
}

// ---------------------------------------------------------------------------
extern "C" void kernel_launch(void* const* d_in, const int* in_sizes, int n_in,
                              void* d_out, int out_size)
{
    const float* x  = (const float*)d_in[0];
    const float* R  = (const float*)d_in[1];
    const float* W1 = (const float*)d_in[2];
    const float* b1 = (const float*)d_in[3];
    const float* W2 = (const float*)d_in[4];
    const float* b2 = (const float*)d_in[5];
    const float* W3 = (const float*)d_in[6];
    const float* b3 = (const float*)d_in[7];
    const float* Q1 = (const float*)d_in[8];
    const float* Q2 = (const float*)d_in[9];
    const float* Q3 = (const float*)d_in[10];

    int B = in_sizes[1] / 9;
    if (B > MAXB) B = MAXB;
    int N = in_sizes[0] / (3 * B);

    precompute_kernel<<<B, 256>>>(R, W1, b1, W2, b2, W3, b3, Q1, Q2, Q3);

    int quads = N >> 2;
    int gx = (quads + THREADS - 1) / THREADS;
    if (N & 3) gx += 1;   // guarantee spare threads for the scalar tail
    dim3 grid(gx, B);
    mf_main_kernel<<<grid, THREADS>>>(x, (float*)d_out, N);
}

// round 7
// speedup vs baseline: 1.1649x; 1.1649x over previous
#include <cuda_runtime.h>
#include <cuda_bf16.h>

// ---------------------------------------------------------------------------
// ParamMakeFeature: fold rotation into MLP weights, then run a packed-f32x2
// 3->15->15->15 MLP, 4 points per thread.
//
// R7 STRUCTURE: weights stored as SCALARS (4 per LDS.128, halving the LDS
// instruction count that saturated L1 at ~62% in R3-R6). f32x2 pairs now run
// over adjacent FEATURES of one point: acc pair j = (h[2j], h[2j+1]).
// Weight pairs (W[2j][f], W[2j+1][f]) are free register aliases of the loaded
// float4; the per-f multiplier (h_f, h_f) costs ~2 MOVs on the idle ALU pipe.
//
// All loops fully unrolled: arrays must be compile-time indexed or ptxas
// demotes them to local memory (R4 regression).
// ---------------------------------------------------------------------------

typedef unsigned long long u64;

#define FEAT 15
#define MAXB 32

// per-batch scalar params, 16 floats per row:
//  rows 0-2 : stage1T row k: col f = W1R[f][k]   (col 15 = 0)
//  row  3   : b1[f]
//  rows 4-18: stage2T row f: col g = W2[g][f]    (col 15 = 0)
//  row  19  : b2[g]
//  rows 20-34: stage3T row f: col p = M3[p][f]
//  row  35  : c3[p]
#define S1_ROW 0
#define S2_ROW 4
#define S3_ROW 20
#define PAR_F 576     // 36 rows * 16 floats

__device__ float g_params[MAXB * PAR_F];

__device__ __forceinline__ u64 pk2(float lo, float hi) {
    u64 r; asm("mov.b64 %0, {%1,%2};" : "=l"(r) : "f"(lo), "f"(hi)); return r;
}
__device__ __forceinline__ void upk2(u64 v, float& lo, float& hi) {
    asm("mov.b64 {%0,%1}, %2;" : "=f"(lo), "=f"(hi) : "l"(v));
}
__device__ __forceinline__ u64 ffma2(u64 a, u64 b, u64 c) {
    u64 d; asm("fma.rn.f32x2 %0, %1, %2, %3;" : "=l"(d) : "l"(a), "l"(b), "l"(c));
    return d;
}

// load one 16-float row as 8 feature-pairs (pairs alias the loaded quads)
__device__ __forceinline__ void load_row(u64 wp[8], const float4* q) {
    float4 q0 = q[0], q1 = q[1], q2 = q[2], q3 = q[3];
    wp[0] = pk2(q0.x, q0.y); wp[1] = pk2(q0.z, q0.w);
    wp[2] = pk2(q1.x, q1.y); wp[3] = pk2(q1.z, q1.w);
    wp[4] = pk2(q2.x, q2.y); wp[5] = pk2(q2.z, q2.w);
    wp[6] = pk2(q3.x, q3.y); wp[7] = pk2(q3.z, q3.w);
}

// ---------------------------------------------------------------------------
// Precompute kernel: one block per batch. Builds W1R = W1*R^T, D-blocks,
// M3 = Dblk*W3, c3 = Dblk*b3; writes SCALAR transposed padded layout.
// ---------------------------------------------------------------------------
__global__ void precompute_kernel(
    const float* __restrict__ R_all,
    const float* __restrict__ W1, const float* __restrict__ b1,
    const float* __restrict__ W2, const float* __restrict__ b2,
    const float* __restrict__ W3, const float* __restrict__ b3,
    const float* __restrict__ Q1, const float* __restrict__ Q2,
    const float* __restrict__ Q3)
{
    const int b = blockIdx.x;
    const int tid = threadIdx.x;

    __shared__ float R[9];
    __shared__ float K2[81];
    __shared__ float K3[729];
    __shared__ float E2[9][5];
    __shared__ float E3[27][7];
    __shared__ float D1[3][3], D2[5][5], D3[7][7];
    __shared__ float M3[15][15], c3[15], W1Rs[15][3];

    if (tid < 9) R[tid] = R_all[b * 9 + tid];
    __syncthreads();

    if (tid < 81) {
        int row = tid / 9, col = tid % 9;
        int i = row / 3, k = row % 3, j = col / 3, l = col % 3;
        K2[tid] = R[i * 3 + j] * R[k * 3 + l];
    } else if (tid >= 96 && tid < 105) {
        int t = tid - 96, p = t / 3, q = t % 3;
        float s = 0.f;
        for (int i = 0; i < 3; i++)
            for (int j = 0; j < 3; j++)
                s += Q1[p * 3 + i] * R[i * 3 + j] * Q1[q * 3 + j];
        D1[p][q] = s;
    } else if (tid >= 112 && tid < 157) {
        int t = tid - 112, f = t / 3, j = t % 3;
        float s = 0.f;
        for (int i = 0; i < 3; i++) s += W1[f * 3 + i] * R[j * 3 + i];
        W1Rs[f][j] = s;
    }
    __syncthreads();

    if (tid < 45) {
        int i = tid / 5, q = tid % 5;
        float s = 0.f;
        for (int j = 0; j < 9; j++) s += K2[i * 9 + j] * Q2[q * 9 + j];
        E2[i][q] = s;
    }
    for (int idx = tid; idx < 729; idx += blockDim.x) {
        int row = idx / 27, col = idx % 27;
        int a = row / 3, m = row % 3, bb = col / 3, nn = col % 3;
        K3[idx] = K2[a * 9 + bb] * R[m * 3 + nn];
    }
    __syncthreads();

    if (tid < 25) {
        int p = tid / 5, q = tid % 5;
        float s = 0.f;
        for (int i = 0; i < 9; i++) s += Q2[p * 9 + i] * E2[i][q];
        D2[p][q] = s;
    } else if (tid >= 32 && tid < 32 + 189) {
        int t = tid - 32, u = t / 7, q = t % 7;
        float s = 0.f;
        for (int v = 0; v < 27; v++) s += K3[u * 27 + v] * Q3[q * 27 + v];
        E3[u][q] = s;
    }
    __syncthreads();

    if (tid < 49) {
        int p = tid / 7, q = tid % 7;
        float s = 0.f;
        for (int u = 0; u < 27; u++) s += Q3[p * 27 + u] * E3[u][q];
        D3[p][q] = s;
    }
    __syncthreads();

    if (tid < 225) {
        int p = tid / 15, f = tid % 15;
        float s = 0.f;
        if (p < 3)       { for (int q = 0; q < 3; q++) s += D1[p][q]     * W3[q * 15 + f]; }
        else if (p < 8)  { for (int q = 0; q < 5; q++) s += D2[p - 3][q] * W3[(3 + q) * 15 + f]; }
        else             { for (int q = 0; q < 7; q++) s += D3[p - 8][q] * W3[(8 + q) * 15 + f]; }
        M3[p][f] = s;
    } else if (tid < 240) {
        int p = tid - 225;
        float s = 0.f;
        if (p < 3)       { for (int q = 0; q < 3; q++) s += D1[p][q]     * b3[q]; }
        else if (p < 8)  { for (int q = 0; q < 5; q++) s += D2[p - 3][q] * b3[3 + q]; }
        else             { for (int q = 0; q < 7; q++) s += D3[p - 8][q] * b3[8 + q]; }
        c3[p] = s;
    }
    __syncthreads();

    // write scalar transposed padded layout
    float* dst = g_params + (size_t)b * PAR_F;
    for (int idx = tid; idx < PAR_F; idx += blockDim.x) {
        float v = 0.f;
        if (idx < S2_ROW * 16) {
            int k = idx >> 4, f = idx & 15;
            if (f < 15) v = (k < 3) ? W1Rs[f][k] : b1[f];
        } else if (idx < S3_ROW * 16) {
            int r = idx - S2_ROW * 16, f = r >> 4, g = r & 15;
            if (g < 15) v = (f < 15) ? W2[g * 15 + f] : b2[g];
        } else {
            int r = idx - S3_ROW * 16, f = r >> 4, p = r & 15;
            if (p < 15) v = (f < 15) ? M3[p][f] : c3[p];
        }
        dst[idx] = v;
    }
}

// ---------------------------------------------------------------------------
// Main kernel: 4 points per thread, feature-paired f32x2 accumulators.
// ---------------------------------------------------------------------------
#define THREADS 128

__global__ __launch_bounds__(THREADS, 3)
void mf_main_kernel(const float* __restrict__ x, float* __restrict__ out, int N)
{
    const int b = blockIdx.y;
    __shared__ __align__(16) float swf[PAR_F];
    {
        const float4* src = (const float4*)(g_params + (size_t)b * PAR_F);
        float4* dstq = (float4*)swf;
        for (int i = threadIdx.x; i < PAR_F / 4; i += THREADS) dstq[i] = src[i];
    }
    __syncthreads();

    const int t = blockIdx.x * THREADS + threadIdx.x;
    const int quads = N >> 2;

    const float* xb = x + (size_t)b * 3 * N;
    float* __restrict__ ob = out + (size_t)b * FEAT * N;
    const float4* swq = (const float4*)swf;

    if (t < quads) {
        float4 a0 = __ldcs((const float4*)(xb                 ) + t);
        float4 a1 = __ldcs((const float4*)(xb + N             ) + t);
        float4 a2 = __ldcs((const float4*)(xb + 2 * (size_t)N ) + t);
        // per-point coords: xc[k][p]
        float xc0[4] = { a0.x, a0.y, a0.z, a0.w };
        float xc1[4] = { a1.x, a1.y, a1.z, a1.w };
        float xc2[4] = { a2.x, a2.y, a2.z, a2.w };

        // ---- stage 1: acc[p][j] = (h1[2j], h1[2j+1]) ----
        u64 acc1[4][8];
        {
            u64 bp[8]; load_row(bp, swq + (S1_ROW + 3) * 4);
            u64 wp[8];
            load_row(wp, swq + (S1_ROW + 0) * 4);
#pragma unroll
            for (int p = 0; p < 4; p++) {
                u64 xd = pk2(xc0[p], xc0[p]);
#pragma unroll
                for (int j = 0; j < 8; j++) acc1[p][j] = ffma2(xd, wp[j], bp[j]);
            }
            load_row(wp, swq + (S1_ROW + 1) * 4);
#pragma unroll
            for (int p = 0; p < 4; p++) {
                u64 xd = pk2(xc1[p], xc1[p]);
#pragma unroll
                for (int j = 0; j < 8; j++) acc1[p][j] = ffma2(xd, wp[j], acc1[p][j]);
            }
            load_row(wp, swq + (S1_ROW + 2) * 4);
#pragma unroll
            for (int p = 0; p < 4; p++) {
                u64 xd = pk2(xc2[p], xc2[p]);
#pragma unroll
                for (int j = 0; j < 8; j++) acc1[p][j] = ffma2(xd, wp[j], acc1[p][j]);
            }
        }

        // relu -> scalar h1[p][f]
        float h1[4][FEAT];
#pragma unroll
        for (int p = 0; p < 4; p++) {
#pragma unroll
            for (int j = 0; j < 7; j++) {
                float lo, hi; upk2(acc1[p][j], lo, hi);
                h1[p][2 * j]     = fmaxf(lo, 0.f);
                h1[p][2 * j + 1] = fmaxf(hi, 0.f);
            }
            { float lo, hi; upk2(acc1[p][7], lo, hi); h1[p][14] = fmaxf(lo, 0.f); (void)hi; }
        }

        // ---- stage 2: acc2[p][j] = (h2[2j], h2[2j+1]) ----
        u64 acc2[4][8];
        {
            u64 bp[8]; load_row(bp, swq + (S2_ROW + 15) * 4);
            u64 wp[8];
            load_row(wp, swq + (S2_ROW + 0) * 4);
#pragma unroll
            for (int p = 0; p < 4; p++) {
                u64 md = pk2(h1[p][0], h1[p][0]);
#pragma unroll
                for (int j = 0; j < 8; j++) acc2[p][j] = ffma2(md, wp[j], bp[j]);
            }
#pragma unroll
            for (int f = 1; f < FEAT; f++) {
                load_row(wp, swq + (S2_ROW + f) * 4);
#pragma unroll
                for (int p = 0; p < 4; p++) {
                    u64 md = pk2(h1[p][f], h1[p][f]);
#pragma unroll
                    for (int j = 0; j < 8; j++) acc2[p][j] = ffma2(md, wp[j], acc2[p][j]);
                }
            }
        }

        // relu -> scalar h2[p][f]
        float h2[4][FEAT];
#pragma unroll
        for (int p = 0; p < 4; p++) {
#pragma unroll
            for (int j = 0; j < 7; j++) {
                float lo, hi; upk2(acc2[p][j], lo, hi);
                h2[p][2 * j]     = fmaxf(lo, 0.f);
                h2[p][2 * j + 1] = fmaxf(hi, 0.f);
            }
            { float lo, hi; upk2(acc2[p][7], lo, hi); h2[p][14] = fmaxf(lo, 0.f); (void)hi; }
        }

        // ---- stage 3: acc3[p][j] = (y[2j], y[2j+1]) ----
        u64 acc3[4][8];
        {
            u64 bp[8]; load_row(bp, swq + (S3_ROW + 15) * 4);
            u64 wp[8];
            load_row(wp, swq + (S3_ROW + 0) * 4);
#pragma unroll
            for (int p = 0; p < 4; p++) {
                u64 md = pk2(h2[p][0], h2[p][0]);
#pragma unroll
                for (int j = 0; j < 8; j++) acc3[p][j] = ffma2(md, wp[j], bp[j]);
            }
#pragma unroll
            for (int f = 1; f < FEAT; f++) {
                load_row(wp, swq + (S3_ROW + f) * 4);
#pragma unroll
                for (int p = 0; p < 4; p++) {
                    u64 md = pk2(h2[p][f], h2[p][f]);
#pragma unroll
                    for (int j = 0; j < 8; j++) acc3[p][j] = ffma2(md, wp[j], acc3[p][j]);
                }
            }
        }

        // ---- store: transpose in-register, one float4 per feature row ----
#pragma unroll
        for (int pp = 0; pp < FEAT; pp++) {
            const int j = pp >> 1;
            float4 st;
            {
                float lo, hi;
                upk2(acc3[0][j], lo, hi); st.x = (pp & 1) ? hi : lo;
                upk2(acc3[1][j], lo, hi); st.y = (pp & 1) ? hi : lo;
                upk2(acc3[2][j], lo, hi); st.z = (pp & 1) ? hi : lo;
                upk2(acc3[3][j], lo, hi); st.w = (pp & 1) ? hi : lo;
            }
            __stcs((float4*)(ob + (size_t)pp * N) + t, st);
        }
    } else {
        // scalar tail for N % 4 leftover points
        const int rem = N & 3;
        const int tp = t - quads;
        if (tp < rem) {
            const int p = (quads << 2) + tp;
            float xv[3] = { xb[p], xb[N + p], xb[2 * (size_t)N + p] };
            float h1[FEAT], h2[FEAT], o[FEAT];
            for (int f = 0; f < FEAT; f++) h1[f] = swf[(S1_ROW + 3) * 16 + f];
            for (int k = 0; k < 3; k++)
                for (int f = 0; f < FEAT; f++)
                    h1[f] += xv[k] * swf[(S1_ROW + k) * 16 + f];
            for (int f = 0; f < FEAT; f++) h1[f] = fmaxf(h1[f], 0.f);

            for (int g = 0; g < FEAT; g++) h2[g] = swf[(S2_ROW + 15) * 16 + g];
            for (int f = 0; f < FEAT; f++)
                for (int g = 0; g < FEAT; g++)
                    h2[g] += h1[f] * swf[(S2_ROW + f) * 16 + g];
            for (int g = 0; g < FEAT; g++) h2[g] = fmaxf(h2[g], 0.f);

            for (int pp = 0; pp < FEAT; pp++) o[pp] = swf[(S3_ROW + 15) * 16 + pp];
            for (int f = 0; f < FEAT; f++)
                for (int pp = 0; pp < FEAT; pp++)
                    o[pp] += h2[f] * swf[(S3_ROW + f) * 16 + pp];
            for (int pp = 0; pp < FEAT; pp++)
                ob[(size_t)pp * N + p] = o[pp];
        }
    }
}

// ---------------------------------------------------------------------------
extern "C" void kernel_launch(void* const* d_in, const int* in_sizes, int n_in,
                              void* d_out, int out_size)
{
    const float* x  = (const float*)d_in[0];
    const float* R  = (const float*)d_in[1];
    const float* W1 = (const float*)d_in[2];
    const float* b1 = (const float*)d_in[3];
    const float* W2 = (const float*)d_in[4];
    const float* b2 = (const float*)d_in[5];
    const float* W3 = (const float*)d_in[6];
    const float* b3 = (const float*)d_in[7];
    const float* Q1 = (const float*)d_in[8];
    const float* Q2 = (const float*)d_in[9];
    const float* Q3 = (const float*)d_in[10];

    int B = in_sizes[1] / 9;
    if (B > MAXB) B = MAXB;
    int N = in_sizes[0] / (3 * B);

    precompute_kernel<<<B, 256>>>(R, W1, b1, W2, b2, W3, b3, Q1, Q2, Q3);

    int quads = N >> 2;
    int gx = (quads + THREADS - 1) / THREADS;
    if (N & 3) gx += 1;   // guarantee spare threads for the scalar tail
    dim3 grid(gx, B);
    mf_main_kernel<<<grid, THREADS>>>(x, (float*)d_out, N);
}